// round 15
// baseline (speedup 1.0000x reference)
#include <cuda_runtime.h>
#include <cstdint>

#define Nn   4096
#define Ee   2048
#define Rr   4
#define HDim 256
#define CAP  (4*1024*1024)
#define NSL  4          // node slices (1024) for edge-CSR
#define ESL  2          // edge slices (1024) for node-CSR
#define SM2  131072     // 1024 rows x 32 feats fp32 panel

// ---------------- scratch ----------------
__device__ float g_rw[Rr];
__device__ float g_s[3*Rr];
__device__ float g_a [Rr*Nn];
__device__ float g_de[Rr*Ee];
__device__ int   g_cntEs[Rr*NSL*Ee];
__device__ int   g_cntNs[Rr*ESL*Nn];
__device__ int   g_eoffs[Rr*NSL*Ee+1];
__device__ int   g_noffs[Rr*ESL*Nn+1];
__device__ int   g_ecurs[Rr*NSL*Ee];
__device__ unsigned g_bm[Rr*Nn*64];
__device__ unsigned short g_eidx[CAP];   // local n (0..1023)
__device__ unsigned short g_nidx[CAP];   // local e (0..1023)
__device__ float g_t  [(size_t)Rr*Ee*HDim];
__device__ float g_hn [(size_t)Rr*Nn*HDim];
__device__ float g_y  [(size_t)Rr*Nn*128];
__device__ float g_bufA[(size_t)Nn*HDim];
__device__ float g_bufB[(size_t)Nn*HDim];
__device__ float g_ws [Rr*HDim*HDim];
__device__ float g_mu[HDim];
__device__ float g_rs[HDim];

// ---------------- prep ----------------
__global__ void k_zero() {
    int i = blockIdx.x*256 + threadIdx.x;
    if (i < Rr*NSL*Ee) { g_cntEs[i] = 0; g_ecurs[i] = 0; }
}

__global__ void k_prep(const float* __restrict__ rel_attn, const float* __restrict__ imp) {
    if (threadIdx.x == 0) {
        float m = -1e30f;
        for (int r = 0; r < Rr; r++) m = fmaxf(m, rel_attn[r]);
        float e[Rr], s = 0.f;
        for (int r = 0; r < Rr; r++) { e[r] = expf(rel_attn[r] - m); s += e[r]; }
        for (int r = 0; r < Rr; r++) g_rw[r] = e[r] / s;
        for (int i = 0; i < 3*Rr; i++) g_s[i] = 1.f / (1.f + expf(-imp[i]));
    }
}

// ---- one pass over H: bitmask + per-half node counts + a + sliced edge counts ----
__global__ void k_pass1(const float* __restrict__ H) {
    int rn = blockIdx.x*8 + (threadIdx.x >> 5);
    int lane = threadIdx.x & 31;
    int r = rn >> 12, n = rn & 4095, sl = n >> 10;
    const float* row = H + (size_t)rn * Ee;
    int cbase = (r*NSL + sl) << 11;
    int c0 = 0, c1 = 0;
    #pragma unroll 8
    for (int w = 0; w < 64; w++) {
        int e = w*32 + lane;
        bool pred = row[e] > 0.5f;
        unsigned b = __ballot_sync(0xFFFFFFFFu, pred);
        if (lane == 0) g_bm[rn*64 + w] = b;
        if (pred) atomicAdd(&g_cntEs[cbase + e], 1);
        if (w < 32) c0 += pred; else c1 += pred;
    }
    #pragma unroll
    for (int s = 16; s; s >>= 1) {
        c0 += __shfl_xor_sync(0xFFFFFFFFu, c0, s);
        c1 += __shfl_xor_sync(0xFFFFFFFFu, c1, s);
    }
    if (lane == 0) {
        g_cntNs[(r*ESL+0)*Nn + n] = c0;
        g_cntNs[(r*ESL+1)*Nn + n] = c1;
        float rw = g_rw[r];
        g_a[rn] = rw * rsqrtf(rw * (float)(c0 + c1) + 1e-8f);
    }
}

__global__ void k_de() {
    int i = blockIdx.x*256 + threadIdx.x;
    if (i < Rr*Ee) {
        int r = i >> 11, e = i & 2047;
        int c = 0;
        #pragma unroll
        for (int sl = 0; sl < NSL; sl++) c += g_cntEs[((r*NSL+sl)<<11) + e];
        float rw = g_rw[r];
        g_de[i] = rsqrtf(rw * (float)c + 1e-8f);
    }
}

// ---------------- single-block exclusive scan (L = 32768) ----------------
__device__ void scan_body(const int* __restrict__ in, int* __restrict__ out, int L) {
    int tid = threadIdx.x;
    int chunk = L >> 10;
    int base = tid * chunk;
    int s = 0;
    for (int j = 0; j < chunk; j++) s += in[base+j];
    __shared__ int sh[1024];
    sh[tid] = s; __syncthreads();
    for (int off = 1; off < 1024; off <<= 1) {
        int v = (tid >= off) ? sh[tid-off] : 0;
        __syncthreads();
        sh[tid] += v;
        __syncthreads();
    }
    int run = (tid == 0) ? 0 : sh[tid-1];
    for (int j = 0; j < chunk; j++) { out[base+j] = run; run += in[base+j]; }
    if (tid == 1023) out[L] = run;
}
__global__ void k_scanE() { scan_body(g_cntEs, g_eoffs, Rr*NSL*Ee); }
__global__ void k_scanN() { scan_body(g_cntNs, g_noffs, Rr*ESL*Nn); }

// ---------------- CSR fill from bitmask (sliced, u16 local indices) ----------------
__global__ void k_fillb() {
    int rn = blockIdx.x;
    int r = rn >> 12, n = rn & 4095, sl = n >> 10;
    __shared__ int sc0, sc1;
    if (threadIdx.x == 0) { sc0 = 0; sc1 = 0; }
    __syncthreads();
    int nb0 = g_noffs[(r*ESL+0)*Nn + n];
    int nb1 = g_noffs[(r*ESL+1)*Nn + n];
    unsigned short nloc = (unsigned short)(n & 1023);
    for (int e = threadIdx.x; e < Ee; e += 256) {
        if ((g_bm[rn*64 + (e >> 5)] >> (e & 31)) & 1u) {
            int le = ((r*NSL + sl) << 11) + e;
            int pe = g_eoffs[le] + atomicAdd(&g_ecurs[le], 1);
            g_eidx[pe] = nloc;
            int pn = (e >= 1024) ? (nb1 + atomicAdd(&sc1, 1)) : (nb0 + atomicAdd(&sc0, 1));
            g_nidx[pn] = (unsigned short)(e & 1023);
        }
    }
}

// ---------------- smem-staged SpMM, register accumulators across slices ----------------
// block = (r, 32-feat chunk fc, 128 output rows); loops all input slices;
// dst[r,o,fc*32+lane] = cout[r,o] * sum_sl sum_{j in list(r,sl,o)} cin[..]*src[.., idx_j, f]
__global__ void __launch_bounds__(512) k_spmm2(
    const float* __restrict__ src, size_t srcR, int F,
    const float* __restrict__ cin, int cinS,
    const float* __restrict__ cout, int coutS,
    const int* __restrict__ offs, const unsigned short* __restrict__ idx,
    float* __restrict__ dst, size_t dstR,
    int nSl, int nOut)
{
    extern __shared__ float sm[];                 // [1024][32]
    int FC = F >> 5;
    int fc = blockIdx.x % FC, r = blockIdx.x / FC;
    int tid = threadIdx.x, lane = tid & 31, wid = tid >> 5;
    int rowbase = blockIdx.y * 128 + wid * 8;     // this warp's 8 output rows

    float acc[8];
    #pragma unroll
    for (int i = 0; i < 8; i++) acc[i] = 0.f;

    for (int sl = 0; sl < nSl; sl++) {
        __syncthreads();                          // prior-slice reads done before overwrite
        const float* sp = src + (size_t)r*srcR + (size_t)sl*1024*F + fc*32;
        const float* ci = cin + r*cinS + sl*1024;
        for (int k = tid; k < 8192; k += 512) {
            int nl = k >> 3, q = k & 7;
            float4 v = *(const float4*)(sp + (size_t)nl*F + q*4);
            float cf = ci[nl];
            v.x *= cf; v.y *= cf; v.z *= cf; v.w *= cf;
            ((float4*)sm)[k] = v;
        }
        __syncthreads();

        int obase = (r*nSl + sl)*nOut + rowbase;
        #pragma unroll
        for (int rr = 0; rr < 8; rr++) {
            int lo = obase + rr;
            int i0 = __ldg(&offs[lo]), i1 = __ldg(&offs[lo+1]);
            float a = 0.f, b = 0.f;
            int i = i0;
            int hend = min(i0 + ((8 - (i0 & 7)) & 7), i1);
            for (; i < hend; i++)
                a += sm[((unsigned)__ldg(&idx[i]))*32 + lane];
            for (; i + 8 <= i1; i += 8) {
                uint4 v = __ldg((const uint4*)(idx + i));   // 8 u16 indices, broadcast
                a += sm[(v.x & 0xFFFFu)*32 + lane];
                b += sm[(v.x >> 16)    *32 + lane];
                a += sm[(v.y & 0xFFFFu)*32 + lane];
                b += sm[(v.y >> 16)    *32 + lane];
                a += sm[(v.z & 0xFFFFu)*32 + lane];
                b += sm[(v.z >> 16)    *32 + lane];
                a += sm[(v.w & 0xFFFFu)*32 + lane];
                b += sm[(v.w >> 16)    *32 + lane];
            }
            for (; i < i1; i++)
                a += sm[((unsigned)__ldg(&idx[i]))*32 + lane];
            acc[rr] += a + b;
        }
    }
    #pragma unroll
    for (int rr = 0; rr < 8; rr++) {
        int o = rowbase + rr;
        dst[(size_t)r*dstR + (size_t)o*F + fc*32 + lane] =
            acc[rr] * __ldg(&cout[r*coutS + o]);
    }
}

// ---------------- scaled weights ----------------
__global__ void k_ws(const float* __restrict__ W, int FN, int layer, int total) {
    int i = blockIdx.x*256 + threadIdx.x;
    if (i < total) g_ws[i] = W[i] * g_s[layer*Rr + i / FN];
}

// ---------------- GEMM: 128x64 tile, 8x4 micro, optional r-batch via grid.z ----------------
__global__ void __launch_bounds__(256) k_gemm(int K, int F, int Nout,
        const float* __restrict__ A, const float* __restrict__ Wt, size_t wStride,
        const float* __restrict__ bias, const float* __restrict__ resid,
        float* __restrict__ C, size_t cStride) {
    const float* W = Wt + blockIdx.z * wStride;
    float* Cp = C + blockIdx.z * cStride;
    __shared__ float As[16][128];
    __shared__ float Bs[16][68];
    int tid = threadIdx.x;
    int bm = blockIdx.x*128, bn = blockIdx.y*64;
    int tx = tid & 15, ty = tid >> 4;
    float acc[8][4] = {};
    int am = tid >> 1, akq = (tid & 1)*8;
    int bk = tid >> 4, bo = (tid & 15)*4;
    for (int k0 = 0; k0 < K; k0 += 16) {
        const float* Ar = A + ((size_t)(k0/F)*Nn + bm + am)*F + (k0 % F) + akq;
        float4 a0 = *(const float4*)Ar;
        float4 a1 = *(const float4*)(Ar + 4);
        As[akq+0][am]=a0.x; As[akq+1][am]=a0.y; As[akq+2][am]=a0.z; As[akq+3][am]=a0.w;
        As[akq+4][am]=a1.x; As[akq+5][am]=a1.y; As[akq+6][am]=a1.z; As[akq+7][am]=a1.w;
        *(float4*)&Bs[bk][bo] = *(const float4*)(W + (size_t)(k0 + bk)*Nout + bn + bo);
        __syncthreads();
        #pragma unroll
        for (int kk = 0; kk < 16; kk++) {
            float4 b  = *(float4*)&Bs[kk][tx*4];
            float4 xA = *(float4*)&As[kk][ty*8];
            float4 xB = *(float4*)&As[kk][ty*8+4];
            float af[8] = {xA.x,xA.y,xA.z,xA.w,xB.x,xB.y,xB.z,xB.w};
            #pragma unroll
            for (int i = 0; i < 8; i++) {
                acc[i][0] += af[i]*b.x; acc[i][1] += af[i]*b.y;
                acc[i][2] += af[i]*b.z; acc[i][3] += af[i]*b.w;
            }
        }
        __syncthreads();
    }
    #pragma unroll
    for (int i = 0; i < 8; i++) {
        int m = bm + ty*8 + i;
        float4 v = make_float4(acc[i][0], acc[i][1], acc[i][2], acc[i][3]);
        if (bias) {
            const float* bp = bias + bn + tx*4;
            v.x += bp[0]; v.y += bp[1]; v.z += bp[2]; v.w += bp[3];
        }
        if (resid) {
            const float* rp = resid + (size_t)m*Nout + bn + tx*4;
            v.x += rp[0]; v.y += rp[1]; v.z += rp[2]; v.w += rp[3];
        }
        *(float4*)(Cp + (size_t)m*Nout + bn + tx*4) = v;
    }
}

// ---------------- final sum over r + bias + residual (layer 3) ----------------
__global__ void k_sum3(const float* __restrict__ b3, const float* __restrict__ X,
                       float* __restrict__ out) {
    int i = blockIdx.x*256 + threadIdx.x;
    const float4* h = (const float4*)g_hn;
    float4 v = h[i];
    float4 v1 = h[131072 + i], v2 = h[262144 + i], v3 = h[393216 + i];
    float4 bb = ((const float4*)b3)[i & 31];
    float4 xx = ((const float4*)X)[i];
    v.x += v1.x + v2.x + v3.x + bb.x + xx.x;
    v.y += v1.y + v2.y + v3.y + bb.y + xx.y;
    v.z += v1.z + v2.z + v3.z + bb.z + xx.z;
    v.w += v1.w + v2.w + v3.w + bb.w + xx.w;
    ((float4*)out)[i] = v;
}

// ---------------- BN stats ----------------
__global__ void k_bnstat(const float* __restrict__ Xin) {
    int h = blockIdx.x;
    float s = 0.f, q = 0.f;
    for (int n = threadIdx.x; n < Nn; n += 256) {
        float v = Xin[(size_t)n*HDim + h];
        s += v; q += v*v;
    }
    __shared__ float sh[256], sh2[256];
    sh[threadIdx.x] = s; sh2[threadIdx.x] = q; __syncthreads();
    for (int st = 128; st; st >>= 1) {
        if (threadIdx.x < st) { sh[threadIdx.x] += sh[threadIdx.x+st]; sh2[threadIdx.x] += sh2[threadIdx.x+st]; }
        __syncthreads();
    }
    if (threadIdx.x == 0) {
        float mu = sh[0] / (float)Nn;
        float var = sh2[0] / (float)Nn - mu*mu;
        g_mu[h] = mu;
        g_rs[h] = rsqrtf(var + 1e-5f);
    }
}

// ---------------- BN + LN + ELU ----------------
__global__ void k_bnln(const float* __restrict__ Xin,
                       const float* __restrict__ bg, const float* __restrict__ bb,
                       const float* __restrict__ lg, const float* __restrict__ lb,
                       float* __restrict__ Out) {
    int n = blockIdx.x, h = threadIdx.x;
    float v = (Xin[(size_t)n*HDim + h] - g_mu[h]) * g_rs[h] * bg[h] + bb[h];
    __shared__ float sh[256], sh2[256];
    sh[h] = v; sh2[h] = v*v; __syncthreads();
    for (int st = 128; st; st >>= 1) {
        if (h < st) { sh[h] += sh[h+st]; sh2[h] += sh2[h+st]; }
        __syncthreads();
    }
    float m = sh[0] / (float)HDim;
    float var = sh2[0] / (float)HDim - m*m;
    float u = (v - m) * rsqrtf(var + 1e-5f) * lg[h] + lb[h];
    Out[(size_t)n*HDim + h] = (u > 0.f) ? u : expm1f(u);
}

// ---------------- launch ----------------
extern "C" void kernel_launch(void* const* d_in, const int* in_sizes, int n_in,
                              void* d_out, int out_size) {
    const float* X   = (const float*)d_in[0];
    const float* H   = (const float*)d_in[1];
    const float* W1  = (const float*)d_in[2];
    const float* W2  = (const float*)d_in[3];
    const float* W3  = (const float*)d_in[4];
    const float* imp = (const float*)d_in[5];
    const float* b1  = (const float*)d_in[6];
    const float* b2  = (const float*)d_in[7];
    const float* b3  = (const float*)d_in[8];
    const float* bng = (const float*)d_in[9];
    const float* bnb = (const float*)d_in[10];
    const float* lng = (const float*)d_in[11];
    const float* lnb = (const float*)d_in[12];
    const float* ra  = (const float*)d_in[13];
    float* out = (float*)d_out;

    cudaFuncSetAttribute(k_spmm2, cudaFuncAttributeMaxDynamicSharedMemorySize, SM2);

    void *pA, *pB, *pHn, *pWs, *pY, *pT, *pa, *pde, *pEo, *pNo, *pEi, *pNi;
    cudaGetSymbolAddress(&pA,  g_bufA);
    cudaGetSymbolAddress(&pB,  g_bufB);
    cudaGetSymbolAddress(&pHn, g_hn);
    cudaGetSymbolAddress(&pWs, g_ws);
    cudaGetSymbolAddress(&pY,  g_y);
    cudaGetSymbolAddress(&pT,  g_t);
    cudaGetSymbolAddress(&pa,  g_a);
    cudaGetSymbolAddress(&pde, g_de);
    cudaGetSymbolAddress(&pEo, g_eoffs);
    cudaGetSymbolAddress(&pNo, g_noffs);
    cudaGetSymbolAddress(&pEi, g_eidx);
    cudaGetSymbolAddress(&pNi, g_nidx);
    float* bufA = (float*)pA;   float* bufB = (float*)pB;
    float* hn   = (float*)pHn;  const float* ws = (const float*)pWs;
    float* ybuf = (float*)pY;   float* tbuf = (float*)pT;
    const float* av = (const float*)pa;  const float* dev = (const float*)pde;
    const int* eoffs = (const int*)pEo;  const int* noffs = (const int*)pNo;
    const unsigned short* eidx = (const unsigned short*)pEi;
    const unsigned short* nidx = (const unsigned short*)pNi;

    // --- structure extraction ---
    k_zero<<<128, 256>>>();
    k_prep<<<1, 32>>>(ra, imp);
    k_pass1<<<Rr*Nn/8, 256>>>(H);
    k_de<<<32, 256>>>();
    k_scanE<<<1, 1024>>>();
    k_scanN<<<1, 1024>>>();
    k_fillb<<<Rr*Nn, 256>>>();

    // --- conv1: F=128 ---
    k_spmm2<<<dim3(4*Rr, Ee/128), 512, SM2>>>(X, 0, 128, av, Nn, dev, Ee,
            eoffs, eidx, tbuf, (size_t)Ee*128, NSL, Ee);
    k_spmm2<<<dim3(4*Rr, Nn/128), 512, SM2>>>(tbuf, (size_t)Ee*128, 128, dev, Ee, av, Nn,
            noffs, nidx, hn, (size_t)Nn*128, ESL, Nn);
    k_ws<<<(Rr*128*256 + 255)/256, 256>>>(W1, 128*256, 0, Rr*128*256);
    k_gemm<<<dim3(Nn/128, 4, 1), 256>>>(Rr*128, 128, 256, hn, ws, 0, b1, nullptr, bufA, 0);
    k_bnstat<<<HDim, 256>>>(bufA);
    k_bnln<<<Nn, HDim>>>(bufA, bng, bnb, lng, lnb, bufB);

    // --- conv2: F=256 ---
    k_spmm2<<<dim3(8*Rr, Ee/128), 512, SM2>>>(bufB, 0, 256, av, Nn, dev, Ee,
            eoffs, eidx, tbuf, (size_t)Ee*256, NSL, Ee);
    k_spmm2<<<dim3(8*Rr, Nn/128), 512, SM2>>>(tbuf, (size_t)Ee*256, 256, dev, Ee, av, Nn,
            noffs, nidx, hn, (size_t)Nn*256, ESL, Nn);
    k_ws<<<(Rr*256*256 + 255)/256, 256>>>(W2, 256*256, 1, Rr*256*256);
    k_gemm<<<dim3(Nn/128, 4, 1), 256>>>(Rr*256, 256, 256, hn, ws, 0, b2, nullptr, bufA, 0);
    k_bnstat<<<HDim, 256>>>(bufA);
    k_bnln<<<Nn, HDim>>>(bufA, bng + HDim, bnb + HDim, lng + HDim, lnb + HDim, bufB);

    // --- conv3 (reordered): Y_r = bufB @ (s_r*W3_r) at F=128, then SpMMs, then sum_r ---
    k_ws<<<(Rr*256*128 + 255)/256, 256>>>(W3, 256*128, 2, Rr*256*128);
    k_gemm<<<dim3(Nn/128, 2, Rr), 256>>>(256, 256, 128, bufB, ws, (size_t)256*128,
                                         nullptr, nullptr, ybuf, (size_t)Nn*128);
    k_spmm2<<<dim3(4*Rr, Ee/128), 512, SM2>>>(ybuf, (size_t)Nn*128, 128, av, Nn, dev, Ee,
            eoffs, eidx, tbuf, (size_t)Ee*128, NSL, Ee);
    k_spmm2<<<dim3(4*Rr, Nn/128), 512, SM2>>>(tbuf, (size_t)Ee*128, 128, dev, Ee, av, Nn,
            noffs, nidx, hn, (size_t)Nn*128, ESL, Nn);
    k_sum3<<<512, 256>>>(b3, X, out);
}

// round 17
// speedup vs baseline: 1.4067x; 1.4067x over previous
#include <cuda_runtime.h>
#include <cuda_fp16.h>
#include <cstdint>

#define Nn   4096
#define Ee   2048
#define Rr   4
#define HDim 256
#define CAP  (4*1024*1024)

// ---------------- scratch ----------------
__device__ float g_rw[Rr];
__device__ float g_s[3*Rr];
__device__ float g_a [Rr*Nn];
__device__ float g_de[Rr*Ee];
__device__ int   g_cntE[Rr*Ee];
__device__ int   g_cntN[Rr*Nn];
__device__ int   g_eoff[Rr*Ee+1];
__device__ int   g_noff[Rr*Nn+1];
__device__ int   g_ecur[Rr*Ee];
__device__ unsigned g_bm[Rr*Nn*64];
__device__ int2  g_epack[CAP];
__device__ int2  g_npack[CAP];
__device__ __half g_th [(size_t)Rr*Ee*HDim];   // fp16 edge intermediate
__device__ float g_hn [(size_t)Rr*Nn*HDim];
__device__ float g_y  [(size_t)Rr*Nn*128];
__device__ float g_bufA[(size_t)Nn*HDim];
__device__ float g_bufB[(size_t)Nn*HDim];
__device__ __half g_bufBh[(size_t)Nn*HDim];    // fp16 copy of activations
__device__ float g_ws [Rr*HDim*HDim];
__device__ float g_mu[HDim];
__device__ float g_rs[HDim];

// ---------------- prep ----------------
__global__ void k_zero() {
    int i = blockIdx.x*256 + threadIdx.x;
    if (i < Rr*Ee) { g_cntE[i] = 0; g_ecur[i] = 0; }
}

__global__ void k_prep(const float* __restrict__ rel_attn, const float* __restrict__ imp) {
    if (threadIdx.x == 0) {
        float m = -1e30f;
        for (int r = 0; r < Rr; r++) m = fmaxf(m, rel_attn[r]);
        float e[Rr], s = 0.f;
        for (int r = 0; r < Rr; r++) { e[r] = expf(rel_attn[r] - m); s += e[r]; }
        for (int r = 0; r < Rr; r++) g_rw[r] = e[r] / s;
        for (int i = 0; i < 3*Rr; i++) g_s[i] = 1.f / (1.f + expf(-imp[i]));
    }
}

// ---- one pass over H: bitmask + node degree + a ----
__global__ void k_pass1(const float* __restrict__ H) {
    int rn = blockIdx.x*8 + (threadIdx.x >> 5);
    int lane = threadIdx.x & 31;
    const float* row = H + (size_t)rn * Ee;
    int c = 0;
    #pragma unroll 8
    for (int w = 0; w < 64; w++) {
        bool pred = row[w*32 + lane] > 0.5f;
        unsigned b = __ballot_sync(0xFFFFFFFFu, pred);
        if (lane == 0) g_bm[rn*64 + w] = b;
        c += pred;
    }
    #pragma unroll
    for (int s = 16; s; s >>= 1) c += __shfl_xor_sync(0xFFFFFFFFu, c, s);
    if (lane == 0) {
        g_cntN[rn] = c;
        float rw = g_rw[rn >> 12];
        g_a[rn] = rw * rsqrtf(rw * (float)c + 1e-8f);
    }
}

// ---- edge degrees from bitmask (no atomics) ----
__global__ void k_degE2() {            // grid Rr*64, block 256
    int r = blockIdx.x >> 6, w = blockIdx.x & 63;
    int tid = threadIdx.x, lane = tid & 31, wid = tid >> 5;
    int c[32];
    #pragma unroll
    for (int b = 0; b < 32; b++) c[b] = 0;
    for (int n = tid; n < Nn; n += 256) {
        unsigned v = g_bm[(r*Nn + n)*64 + w];
        #pragma unroll
        for (int b = 0; b < 32; b++) c[b] += (v >> b) & 1;
    }
    __shared__ int sh[8][32];
    #pragma unroll
    for (int b = 0; b < 32; b++) {
        int v = c[b];
        #pragma unroll
        for (int s = 16; s; s >>= 1) v += __shfl_xor_sync(0xFFFFFFFFu, v, s);
        if (lane == 0) sh[wid][b] = v;
    }
    __syncthreads();
    if (tid < 32) {
        int t = 0;
        #pragma unroll
        for (int i = 0; i < 8; i++) t += sh[i][tid];
        g_cntE[(r << 11) + w*32 + tid] = t;
    }
}

__global__ void k_de() {
    int i = blockIdx.x*256 + threadIdx.x;
    if (i < Rr*Ee) {
        float rw = g_rw[i >> 11];
        g_de[i] = rsqrtf(rw * (float)g_cntE[i] + 1e-8f);
    }
}

// ---------------- single-block exclusive scan ----------------
__device__ void scan_body(const int* __restrict__ in, int* __restrict__ out, int L) {
    int tid = threadIdx.x;
    int chunk = L >> 10;
    int base = tid * chunk;
    int s = 0;
    for (int j = 0; j < chunk; j++) s += in[base+j];
    __shared__ int sh[1024];
    sh[tid] = s; __syncthreads();
    for (int off = 1; off < 1024; off <<= 1) {
        int v = (tid >= off) ? sh[tid-off] : 0;
        __syncthreads();
        sh[tid] += v;
        __syncthreads();
    }
    int run = (tid == 0) ? 0 : sh[tid-1];
    for (int j = 0; j < chunk; j++) { out[base+j] = run; run += in[base+j]; }
    if (tid == 1023) out[L] = run;
}
__global__ void k_scanE() { scan_body(g_cntE, g_eoff, Rr*Ee); }
__global__ void k_scanN() { scan_body(g_cntN, g_noff, Rr*Nn); }

// ---------------- CSR fill from bitmask ----------------
__global__ void k_fillb() {
    int rn = blockIdx.x;
    int r = rn >> 12, n = rn & 4095;
    __shared__ int sc;
    if (threadIdx.x == 0) sc = 0;
    __syncthreads();
    float arn = g_a[rn];
    int nbase = g_noff[rn];
    for (int e = threadIdx.x; e < Ee; e += 256) {
        if ((g_bm[rn*64 + (e >> 5)] >> (e & 31)) & 1u) {
            int re = (r << 11) + e;
            int pe = g_eoff[re] + atomicAdd(&g_ecur[re], 1);
            if (pe < CAP) g_epack[pe] = make_int2(n, __float_as_int(arn));
            int pn = nbase + atomicAdd(&sc, 1);
            if (pn < CAP) g_npack[pn] = make_int2(e, __float_as_int(g_de[re]));
        }
    }
}

// ---------------- sparse stage 1: t[re,:] = de * sum a[n]*src[n,:] (write fp16) ----------------
template<int F, typename T>
__global__ void __launch_bounds__(128) k_spmm_t(const T* __restrict__ Xin, int rstride,
                                                __half* __restrict__ tout) {
    int re = blockIdx.x;
    int i0 = g_eoff[re], i1 = g_eoff[re+1];
    int tid = threadIdx.x;
    const T* Xp = Xin + (size_t)(re >> 11) * rstride;
    if constexpr (F == 256) {
        float ax = 0.f, ay = 0.f;
        if constexpr (sizeof(T) == 4) {
            const float2* X2 = reinterpret_cast<const float2*>(Xp);
            #pragma unroll 4
            for (int i = i0; i < i1; i++) {
                int2 p = __ldg(&g_epack[i]);
                float c = __int_as_float(p.y);
                float2 x = __ldg(&X2[(size_t)p.x*128 + tid]);
                ax += c * x.x; ay += c * x.y;
            }
        } else {
            const __half2* X2 = reinterpret_cast<const __half2*>(Xp);
            #pragma unroll 4
            for (int i = i0; i < i1; i++) {
                int2 p = __ldg(&g_epack[i]);
                float c = __int_as_float(p.y);
                float2 x = __half22float2(__ldg(&X2[(size_t)p.x*128 + tid]));
                ax += c * x.x; ay += c * x.y;
            }
        }
        float d = g_de[re];
        reinterpret_cast<__half2*>(tout)[(size_t)re*128 + tid] =
            __floats2half2_rn(d*ax, d*ay);
    } else {
        float acc = 0.f;
        #pragma unroll 4
        for (int i = i0; i < i1; i++) {
            int2 p = __ldg(&g_epack[i]);
            acc += __int_as_float(p.y) * (float)__ldg(&Xp[(size_t)p.x*128 + tid]);
        }
        tout[(size_t)re*128 + tid] = __float2half_rn(g_de[re] * acc);
    }
}

// ---------------- sparse stage 2: hn[rn,:] = a * sum de*t[e,:] (read fp16, write fp32) ----------------
template<int F>
__global__ void __launch_bounds__(128) k_spmm_n(const __half* __restrict__ th) {
    int rn = blockIdx.x;
    int r = rn >> 12;
    int i0 = g_noff[rn], i1 = g_noff[rn+1];
    int tid = threadIdx.x;
    if constexpr (F == 256) {
        const __half2* T2 = reinterpret_cast<const __half2*>(th) + (size_t)r*Ee*128;
        float ax = 0.f, ay = 0.f;
        #pragma unroll 4
        for (int i = i0; i < i1; i++) {
            int2 p = __ldg(&g_npack[i]);
            float c = __int_as_float(p.y);
            float2 x = __half22float2(__ldg(&T2[(size_t)p.x*128 + tid]));
            ax += c * x.x; ay += c * x.y;
        }
        float a = g_a[rn];
        reinterpret_cast<float2*>(g_hn)[(size_t)rn*128 + tid] = make_float2(a*ax, a*ay);
    } else {
        const __half* T1 = th + (size_t)r*Ee*128;
        float acc = 0.f;
        #pragma unroll 4
        for (int i = i0; i < i1; i++) {
            int2 p = __ldg(&g_npack[i]);
            acc += __int_as_float(p.y) * __half2float(__ldg(&T1[(size_t)p.x*128 + tid]));
        }
        g_hn[(size_t)rn*128 + tid] = g_a[rn] * acc;
    }
}

// ---------------- scaled weights ----------------
__global__ void k_ws(const float* __restrict__ W, int FN, int layer, int total) {
    int i = blockIdx.x*256 + threadIdx.x;
    if (i < total) g_ws[i] = W[i] * g_s[layer*Rr + i / FN];
}

// ---------------- GEMM: 128x64 tile, 8x4 micro, optional r-batch via grid.z ----------------
__global__ void __launch_bounds__(256) k_gemm(int K, int F, int Nout,
        const float* __restrict__ A, const float* __restrict__ Wt, size_t wStride,
        const float* __restrict__ bias, const float* __restrict__ resid,
        float* __restrict__ C, size_t cStride) {
    const float* W = Wt + blockIdx.z * wStride;
    float* Cp = C + blockIdx.z * cStride;
    __shared__ float As[16][128];
    __shared__ float Bs[16][68];
    int tid = threadIdx.x;
    int bm = blockIdx.x*128, bn = blockIdx.y*64;
    int tx = tid & 15, ty = tid >> 4;
    float acc[8][4] = {};
    int am = tid >> 1, akq = (tid & 1)*8;
    int bk = tid >> 4, bo = (tid & 15)*4;
    for (int k0 = 0; k0 < K; k0 += 16) {
        const float* Ar = A + ((size_t)(k0/F)*Nn + bm + am)*F + (k0 % F) + akq;
        float4 a0 = *(const float4*)Ar;
        float4 a1 = *(const float4*)(Ar + 4);
        As[akq+0][am]=a0.x; As[akq+1][am]=a0.y; As[akq+2][am]=a0.z; As[akq+3][am]=a0.w;
        As[akq+4][am]=a1.x; As[akq+5][am]=a1.y; As[akq+6][am]=a1.z; As[akq+7][am]=a1.w;
        *(float4*)&Bs[bk][bo] = *(const float4*)(W + (size_t)(k0 + bk)*Nout + bn + bo);
        __syncthreads();
        #pragma unroll
        for (int kk = 0; kk < 16; kk++) {
            float4 b  = *(float4*)&Bs[kk][tx*4];
            float4 xA = *(float4*)&As[kk][ty*8];
            float4 xB = *(float4*)&As[kk][ty*8+4];
            float af[8] = {xA.x,xA.y,xA.z,xA.w,xB.x,xB.y,xB.z,xB.w};
            #pragma unroll
            for (int i = 0; i < 8; i++) {
                acc[i][0] += af[i]*b.x; acc[i][1] += af[i]*b.y;
                acc[i][2] += af[i]*b.z; acc[i][3] += af[i]*b.w;
            }
        }
        __syncthreads();
    }
    #pragma unroll
    for (int i = 0; i < 8; i++) {
        int m = bm + ty*8 + i;
        float4 v = make_float4(acc[i][0], acc[i][1], acc[i][2], acc[i][3]);
        if (bias) {
            const float* bp = bias + bn + tx*4;
            v.x += bp[0]; v.y += bp[1]; v.z += bp[2]; v.w += bp[3];
        }
        if (resid) {
            const float* rp = resid + (size_t)m*Nout + bn + tx*4;
            v.x += rp[0]; v.y += rp[1]; v.z += rp[2]; v.w += rp[3];
        }
        *(float4*)(Cp + (size_t)m*Nout + bn + tx*4) = v;
    }
}

// ---------------- final sum over r + bias + residual (layer 3) ----------------
__global__ void k_sum3(const float* __restrict__ b3, const float* __restrict__ X,
                       float* __restrict__ out) {
    int i = blockIdx.x*256 + threadIdx.x;
    const float4* h = (const float4*)g_hn;
    float4 v = h[i];
    float4 v1 = h[131072 + i], v2 = h[262144 + i], v3 = h[393216 + i];
    float4 bb = ((const float4*)b3)[i & 31];
    float4 xx = ((const float4*)X)[i];
    v.x += v1.x + v2.x + v3.x + bb.x + xx.x;
    v.y += v1.y + v2.y + v3.y + bb.y + xx.y;
    v.z += v1.z + v2.z + v3.z + bb.z + xx.z;
    v.w += v1.w + v2.w + v3.w + bb.w + xx.w;
    ((float4*)out)[i] = v;
}

// ---------------- BN stats ----------------
__global__ void k_bnstat(const float* __restrict__ Xin) {
    int h = blockIdx.x;
    float s = 0.f, q = 0.f;
    for (int n = threadIdx.x; n < Nn; n += 256) {
        float v = Xin[(size_t)n*HDim + h];
        s += v; q += v*v;
    }
    __shared__ float sh[256], sh2[256];
    sh[threadIdx.x] = s; sh2[threadIdx.x] = q; __syncthreads();
    for (int st = 128; st; st >>= 1) {
        if (threadIdx.x < st) { sh[threadIdx.x] += sh[threadIdx.x+st]; sh2[threadIdx.x] += sh2[threadIdx.x+st]; }
        __syncthreads();
    }
    if (threadIdx.x == 0) {
        float mu = sh[0] / (float)Nn;
        float var = sh2[0] / (float)Nn - mu*mu;
        g_mu[h] = mu;
        g_rs[h] = rsqrtf(var + 1e-5f);
    }
}

// ---------------- BN + LN + ELU (writes fp32 + fp16 copies) ----------------
__global__ void k_bnln(const float* __restrict__ Xin,
                       const float* __restrict__ bg, const float* __restrict__ bb,
                       const float* __restrict__ lg, const float* __restrict__ lb,
                       float* __restrict__ Out, __half* __restrict__ Outh) {
    int n = blockIdx.x, h = threadIdx.x;
    float v = (Xin[(size_t)n*HDim + h] - g_mu[h]) * g_rs[h] * bg[h] + bb[h];
    __shared__ float sh[256], sh2[256];
    sh[h] = v; sh2[h] = v*v; __syncthreads();
    for (int st = 128; st; st >>= 1) {
        if (h < st) { sh[h] += sh[h+st]; sh2[h] += sh2[h+st]; }
        __syncthreads();
    }
    float m = sh[0] / (float)HDim;
    float var = sh2[0] / (float)HDim - m*m;
    float u = (v - m) * rsqrtf(var + 1e-5f) * lg[h] + lb[h];
    float o = (u > 0.f) ? u : expm1f(u);
    Out[(size_t)n*HDim + h] = o;
    Outh[(size_t)n*HDim + h] = __float2half_rn(o);
}

// ---------------- launch ----------------
extern "C" void kernel_launch(void* const* d_in, const int* in_sizes, int n_in,
                              void* d_out, int out_size) {
    const float* X   = (const float*)d_in[0];
    const float* H   = (const float*)d_in[1];
    const float* W1  = (const float*)d_in[2];
    const float* W2  = (const float*)d_in[3];
    const float* W3  = (const float*)d_in[4];
    const float* imp = (const float*)d_in[5];
    const float* b1  = (const float*)d_in[6];
    const float* b2  = (const float*)d_in[7];
    const float* b3  = (const float*)d_in[8];
    const float* bng = (const float*)d_in[9];
    const float* bnb = (const float*)d_in[10];
    const float* lng = (const float*)d_in[11];
    const float* lnb = (const float*)d_in[12];
    const float* ra  = (const float*)d_in[13];
    float* out = (float*)d_out;

    void *pA, *pB, *pBh, *pHn, *pWs, *pY, *pTh;
    cudaGetSymbolAddress(&pA,  g_bufA);
    cudaGetSymbolAddress(&pB,  g_bufB);
    cudaGetSymbolAddress(&pBh, g_bufBh);
    cudaGetSymbolAddress(&pHn, g_hn);
    cudaGetSymbolAddress(&pWs, g_ws);
    cudaGetSymbolAddress(&pY,  g_y);
    cudaGetSymbolAddress(&pTh, g_th);
    float* bufA = (float*)pA;   float* bufB = (float*)pB;
    __half* bufBh = (__half*)pBh;
    float* hn   = (float*)pHn;  const float* ws = (const float*)pWs;
    float* ybuf = (float*)pY;   __half* th = (__half*)pTh;

    // --- structure extraction: one pass over H ---
    k_zero<<<32, 256>>>();
    k_prep<<<1, 32>>>(ra, imp);
    k_pass1<<<Rr*Nn/8, 256>>>(H);
    k_degE2<<<Rr*64, 256>>>();
    k_de<<<32, 256>>>();
    k_scanE<<<1, 1024>>>();
    k_scanN<<<1, 1024>>>();
    k_fillb<<<Rr*Nn, 256>>>();

    // --- conv1: F=128 -> 256 ---
    k_spmm_t<128,float><<<Rr*Ee, 128>>>(X, 0, th);
    k_spmm_n<128><<<Rr*Nn, 128>>>(th);
    k_ws<<<(Rr*128*256 + 255)/256, 256>>>(W1, 128*256, 0, Rr*128*256);
    k_gemm<<<dim3(Nn/128, 4, 1), 256>>>(Rr*128, 128, 256, hn, ws, 0, b1, nullptr, bufA, 0);
    k_bnstat<<<HDim, 256>>>(bufA);
    k_bnln<<<Nn, HDim>>>(bufA, bng, bnb, lng, lnb, bufB, bufBh);

    // --- conv2: 256 -> 256 (stage-1 gathers fp16 activations) ---
    k_spmm_t<256,__half><<<Rr*Ee, 128>>>(bufBh, 0, th);
    k_spmm_n<256><<<Rr*Nn, 128>>>(th);
    k_ws<<<(Rr*256*256 + 255)/256, 256>>>(W2, 256*256, 1, Rr*256*256);
    k_gemm<<<dim3(Nn/128, 4, 1), 256>>>(Rr*256, 256, 256, hn, ws, 0, b2, nullptr, bufA, 0);
    k_bnstat<<<HDim, 256>>>(bufA);
    k_bnln<<<Nn, HDim>>>(bufA, bng + HDim, bnb + HDim, lng + HDim, lnb + HDim, bufB, bufBh);

    // --- conv3 (reordered): Y_r = bufB @ (s_r*W3_r) at F=128, then SpMMs, then sum_r ---
    k_ws<<<(Rr*256*128 + 255)/256, 256>>>(W3, 256*128, 2, Rr*256*128);
    k_gemm<<<dim3(Nn/128, 2, Rr), 256>>>(256, 256, 128, bufB, ws, (size_t)256*128,
                                         nullptr, nullptr, ybuf, (size_t)Nn*128);
    k_spmm_t<128,float><<<Rr*Ee, 128>>>(ybuf, Nn*128, th);
    k_spmm_n<128><<<Rr*Nn, 128>>>(th);
    k_sum3<<<512, 256>>>(b3, X, out);
}